// round 15
// baseline (speedup 1.0000x reference)
#include <cuda_runtime.h>

#define KSZ   5
#define CIN   3
#define BATCH 2
#define HH    48
#define KN    16
#define OH    44
#define PP    1936            // OH*OH
#define IMG_ELEMS (CIN*HH*HH) // 6912
#define WSZ   (CIN*KSZ*KSZ)   // 75

#define TILE    128
#define NT      16            // tiles per dim
#define NUPPER  (NT * (NT + 1) / 2)   // 136 upper-triangular tiles
#define QV      (PP / 4)      // 484 float4 per row

#define KNH          8                                 // kn planes per vblock (R13 optimum)
#define GRAM_CTAS    (NUPPER * BATCH)                  // 272
#define GRID_SZ      296                               // one full wave at 2 CTAs/SM (148 SMs)
#define MU_CTAS      (GRID_SZ - GRAM_CTAS)             // 24
#define SCALE_TOTAL  (BATCH * PP * QV)                 // 1,874,048 vec4 units
#define SCALE_BLOCKS ((SCALE_TOTAL + 255) / 256)       // 7321 per kn-half
#define TOT_VB       (2 * SCALE_BLOCKS)                // 14642
#define VB_PER       ((TOT_VB + GRID_SZ - 1) / GRID_SZ) // 50

typedef unsigned long long u64;

// 30 MB scratch for the unscaled Gram matrix xxT[b, p, q]
__device__ float g_xxT[(size_t)BATCH * PP * PP];
// Monotonic grid-barrier counter (epoch trick: never reset, replay-safe)
__device__ u64 g_bar;

__device__ __forceinline__ u64 pack2(float lo, float hi) {
    u64 r; asm("mov.b64 %0, {%1,%2};" : "=l"(r) : "f"(lo), "f"(hi)); return r;
}
__device__ __forceinline__ void fma2(u64 &d, u64 a, u64 b) {
    asm("fma.rn.f32x2 %0, %1, %2, %0;" : "+l"(d) : "l"(a), "l"(b));
}
__device__ __forceinline__ float2 unpack2(u64 v) {
    float2 f; asm("mov.b64 {%0,%1}, %2;" : "=f"(f.x), "=f"(f.y) : "l"(v)); return f;
}

// ---------------------------------------------------------------------------
// Single persistent kernel, grid = 296 CTAs (exactly one wave at 2 CTAs/SM,
// guaranteed by __launch_bounds__(256,2) => <=128 regs => spin barrier safe).
//
// Phase 1: CTAs [0,272)   : upper-triangular 128x128 Gram tile (stored twice).
//          CTAs [272,296) : mean conv planes (hidden under gram).
// Grid barrier (epoch-based monotonic counter; CUDA-graph-replay safe).
// Phase 2: all CTAs stream sigma = xxT * softplus(w_sigma[kn]); each CTA owns
//          a CONTIGUOUS run of ~50 vblocks (KNH=8 planes per vblock).
// ---------------------------------------------------------------------------
__global__ __launch_bounds__(256, 2)
void vdp_fused_kernel(const float* __restrict__ mu_in,
                      const float* __restrict__ w_mu,
                      const float* __restrict__ w_sigma,
                      float* __restrict__ mu_out,
                      float* __restrict__ sigma)
{
    __shared__ float img[IMG_ELEMS];
    __shared__ float sp[KN];

    const int tid  = threadIdx.x;
    const int bidx = blockIdx.x;

    if (tid < KN) sp[tid] = log1pf(expf(w_sigma[tid]));

    if (bidx < GRAM_CTAS) {
        // =================== Phase 1a: Gram tile ===========================
        const int b = (bidx >= NUPPER) ? 1 : 0;
        const int t = bidx - b * NUPPER;

        const float* src = mu_in + b * IMG_ELEMS;
        for (int i = tid; i < IMG_ELEMS; i += 256) img[i] = src[i];
        __syncthreads();

        int ti = 0, rem = t;
        while (rem >= NT - ti) { rem -= NT - ti; ti++; }
        const int tj = ti + rem;

        const int tx = tid & 15;
        const int ty = tid >> 4;
        const int p0 = ti * TILE;
        const int q0 = tj * TILE;

        int basep[8], baseq[8];
        #pragma unroll
        for (int r = 0; r < 8; r++) {
            int p = p0 + ty * 8 + r;
            int pc = (p < PP) ? p : 0;
            int ph = pc / OH, pw = pc - ph * OH;
            basep[r] = ph * HH + pw;
        }
        #pragma unroll
        for (int s = 0; s < 8; s++) {
            int q = q0 + tx + s * 16;
            int qc = (q < PP) ? q : 0;
            int qh = qc / OH, qw = qc - qh * OH;
            baseq[s] = qh * HH + qw;
        }

        u64 acc[8][4];
        #pragma unroll
        for (int r = 0; r < 8; r++)
            #pragma unroll
            for (int h = 0; h < 4; h++) acc[r][h] = 0ULL;

        #pragma unroll 1
        for (int c = 0; c < CIN; c++) {
            int bp[8], bq[8];
            const int coff = c * (HH * HH);
            #pragma unroll
            for (int r = 0; r < 8; r++) bp[r] = basep[r] + coff;
            #pragma unroll
            for (int s = 0; s < 8; s++) bq[s] = baseq[s] + coff;

            #pragma unroll
            for (int i = 0; i < KSZ; i++) {
                #pragma unroll
                for (int j = 0; j < KSZ; j++) {
                    const int off = i * HH + j;
                    float av[8], bv[8];
                    #pragma unroll
                    for (int r = 0; r < 8; r++) av[r] = img[bp[r] + off];
                    #pragma unroll
                    for (int s = 0; s < 8; s++) bv[s] = img[bq[s] + off];

                    u64 avp[8], bvp[4];
                    #pragma unroll
                    for (int r = 0; r < 8; r++) avp[r] = pack2(av[r], av[r]);
                    #pragma unroll
                    for (int h = 0; h < 4; h++) bvp[h] = pack2(bv[2*h], bv[2*h+1]);

                    #pragma unroll
                    for (int r = 0; r < 8; r++)
                        #pragma unroll
                        for (int h = 0; h < 4; h++)
                            fma2(acc[r][h], avp[r], bvp[h]);
                }
            }
        }

        float* gbase = g_xxT + (size_t)b * PP * PP;

        #pragma unroll
        for (int r = 0; r < 8; r++) {
            int p = p0 + ty * 8 + r;
            if (p >= PP) continue;
            float* row = gbase + (size_t)p * PP;
            #pragma unroll
            for (int h = 0; h < 4; h++) {
                float2 f = unpack2(acc[r][h]);
                int q1 = q0 + tx + 32 * h;
                int q2 = q1 + 16;
                if (q1 < PP) row[q1] = f.x;
                if (q2 < PP) row[q2] = f.y;
            }
        }

        if (ti != tj) {
            const int pbase = p0 + ty * 8;
            #pragma unroll
            for (int s = 0; s < 8; s++) {
                int q = q0 + tx + 16 * s;
                if (q >= PP) continue;
                float4 v0, v1;
                {
                    float2 a0 = unpack2(acc[0][s >> 1]);
                    float2 a1 = unpack2(acc[1][s >> 1]);
                    float2 a2 = unpack2(acc[2][s >> 1]);
                    float2 a3 = unpack2(acc[3][s >> 1]);
                    float2 a4 = unpack2(acc[4][s >> 1]);
                    float2 a5 = unpack2(acc[5][s >> 1]);
                    float2 a6 = unpack2(acc[6][s >> 1]);
                    float2 a7 = unpack2(acc[7][s >> 1]);
                    if (s & 1) {
                        v0 = make_float4(a0.y, a1.y, a2.y, a3.y);
                        v1 = make_float4(a4.y, a5.y, a6.y, a7.y);
                    } else {
                        v0 = make_float4(a0.x, a1.x, a2.x, a3.x);
                        v1 = make_float4(a4.x, a5.x, a6.x, a7.x);
                    }
                }
                float* row = gbase + (size_t)q * PP + pbase;
                if (pbase < PP)     *(float4*)row       = v0;
                if (pbase + 4 < PP) *(float4*)(row + 4) = v1;
            }
        }
    } else {
        // =================== Phase 1b: mu conv =============================
        const int mi = bidx - GRAM_CTAS;     // 0..23
        #pragma unroll 1
        for (int m = mi; m < BATCH * KN; m += MU_CTAS) {
            const int b  = m >> 4;
            const int kn = m & 15;
            const float* im = mu_in + b * IMG_ELEMS;
            const float* w  = w_mu + kn * WSZ;
            float* outp = mu_out + ((size_t)b * KN + kn) * (OH * OH);

            #pragma unroll 1
            for (int pass = 0; pass < 2; pass++) {
                int base[4];
                bool valid[4];
                #pragma unroll
                for (int k = 0; k < 4; k++) {
                    int pos = tid + (pass * 4 + k) * 256;
                    valid[k] = (pos < OH * OH);
                    int pc = valid[k] ? pos : 0;
                    int oy = pc / OH, ox = pc - oy * OH;
                    base[k] = oy * HH + ox;
                }
                float acc[4] = {0.f, 0.f, 0.f, 0.f};
                #pragma unroll
                for (int c = 0; c < CIN; c++) {
                    const float* imc = im + c * HH * HH;
                    const float* wc  = w + c * KSZ * KSZ;
                    #pragma unroll
                    for (int i = 0; i < KSZ; i++)
                        #pragma unroll
                        for (int j = 0; j < KSZ; j++) {
                            const float wv = __ldg(&wc[i * KSZ + j]);
                            const int off = i * HH + j;
                            #pragma unroll
                            for (int k = 0; k < 4; k++)
                                acc[k] = fmaf(__ldg(&imc[base[k] + off]), wv, acc[k]);
                        }
                }
                #pragma unroll
                for (int k = 0; k < 4; k++)
                    if (valid[k]) outp[tid + (pass * 4 + k) * 256] = acc[k];
            }
        }
    }

    // =================== Grid barrier (epoch counter) =======================
    __threadfence();      // make this CTA's global stores visible device-wide
    __syncthreads();      // all threads of the CTA done before thread0 arrives
    if (tid == 0) {
        u64 ticket = atomicAdd(&g_bar, 1ULL);
        u64 target = (ticket / GRID_SZ + 1ULL) * GRID_SZ;
        u64 v;
        do {
            asm volatile("ld.acquire.gpu.u64 %0, [%1];" : "=l"(v) : "l"(&g_bar));
        } while (v < target);
    }
    __syncthreads();

    // =================== Phase 2: scale-broadcast ===========================
    const size_t planeStride = (size_t)PP * PP;
    const int vb0 = bidx * VB_PER;
    const int vb1 = (vb0 + VB_PER < TOT_VB) ? vb0 + VB_PER : TOT_VB;

    #pragma unroll 1
    for (int vb = vb0; vb < vb1; vb++) {
        const int khalf = (vb >= SCALE_BLOCKS) ? 1 : 0;
        const int blk   = vb - khalf * SCALE_BLOCKS;
        const int idx   = blk * 256 + tid;
        if (idx >= SCALE_TOTAL) continue;

        const int qv = idx % QV;
        const int p  = (idx / QV) % PP;
        const int b  = idx / (QV * PP);

        const float4 v = __ldcg((const float4*)&g_xxT[((size_t)b * PP + p) * PP + qv * 4]);

        float* o = sigma + ((size_t)b * KN + khalf * KNH) * planeStride
                         + (size_t)p * PP + qv * 4;
        #pragma unroll
        for (int k = 0; k < KNH; k++) {
            const float s = sp[khalf * KNH + k];
            float4 w;
            w.x = v.x * s; w.y = v.y * s; w.z = v.z * s; w.w = v.w * s;
            __stcs((float4*)o, w);
            o += planeStride;
        }
    }
}

extern "C" void kernel_launch(void* const* d_in, const int* in_sizes, int n_in,
                              void* d_out, int out_size)
{
    const float* mu_in   = (const float*)d_in[0];
    const float* w_mu    = (const float*)d_in[1];
    const float* w_sigma = (const float*)d_in[2];

    float* out    = (float*)d_out;
    float* mu_out = out;
    float* sigma  = out + (size_t)BATCH * KN * OH * OH;

    vdp_fused_kernel<<<GRID_SZ, 256>>>(mu_in, w_mu, w_sigma, mu_out, sigma);
}

// round 16
// speedup vs baseline: 1.0003x; 1.0003x over previous
#include <cuda_runtime.h>

#define KSZ   5
#define CIN   3
#define BATCH 2
#define HH    48
#define KN    16
#define OH    44
#define PP    1936            // OH*OH
#define IMG_ELEMS (CIN*HH*HH) // 6912
#define WSZ   (CIN*KSZ*KSZ)   // 75

#define TILE    128
#define NT      16            // tiles per dim
#define NUPPER  (NT * (NT + 1) / 2)   // 136 upper-triangular tiles
#define QV      (PP / 4)      // 484 float4 per row

#define KNH          8                                 // kn planes per vblock (R13 optimum)
#define GRAM_CTAS    (NUPPER * BATCH)                  // 272
#define GRID_SZ      296                               // one full wave at 2 CTAs/SM (148 SMs)
#define MU_CTAS      (GRID_SZ - GRAM_CTAS)             // 24
#define SCALE_TOTAL  (BATCH * PP * QV)                 // 1,874,048 vec4 units
#define SCALE_BLOCKS ((SCALE_TOTAL + 255) / 256)       // 7321 per kn-half
#define TOT_VB       (2 * SCALE_BLOCKS)                // 14642
#define VB_PER       ((TOT_VB + GRID_SZ - 1) / GRID_SZ) // 50

typedef unsigned long long u64;

// 30 MB scratch for the unscaled Gram matrix xxT[b, p, q]
__device__ float g_xxT[(size_t)BATCH * PP * PP];
// Monotonic grid-barrier counter (epoch trick: never reset, replay-safe)
__device__ u64 g_bar;

__device__ __forceinline__ u64 pack2(float lo, float hi) {
    u64 r; asm("mov.b64 %0, {%1,%2};" : "=l"(r) : "f"(lo), "f"(hi)); return r;
}
__device__ __forceinline__ void fma2(u64 &d, u64 a, u64 b) {
    asm("fma.rn.f32x2 %0, %1, %2, %0;" : "+l"(d) : "l"(a), "l"(b));
}
__device__ __forceinline__ float2 unpack2(u64 v) {
    float2 f; asm("mov.b64 {%0,%1}, %2;" : "=f"(f.x), "=f"(f.y) : "l"(v)); return f;
}

// ---------------------------------------------------------------------------
// Single persistent kernel, grid = 296 CTAs (exactly one wave at 2 CTAs/SM,
// guaranteed by __launch_bounds__(256,2) => <=128 regs => spin barrier safe).
//
// Phase 1: CTAs [0,272)   : upper-triangular 128x128 Gram tile (stored twice).
//          CTAs [272,296) : mean conv planes (hidden under gram).
// Grid barrier (epoch-based monotonic counter; CUDA-graph-replay safe).
// Phase 2: all CTAs stream sigma = xxT * softplus(w_sigma[kn]); each CTA owns
//          a CONTIGUOUS run of ~50 vblocks (KNH=8 planes per vblock).
// ---------------------------------------------------------------------------
__global__ __launch_bounds__(256, 2)
void vdp_fused_kernel(const float* __restrict__ mu_in,
                      const float* __restrict__ w_mu,
                      const float* __restrict__ w_sigma,
                      float* __restrict__ mu_out,
                      float* __restrict__ sigma)
{
    __shared__ float img[IMG_ELEMS];
    __shared__ float sp[KN];

    const int tid  = threadIdx.x;
    const int bidx = blockIdx.x;

    if (tid < KN) sp[tid] = log1pf(expf(w_sigma[tid]));

    if (bidx < GRAM_CTAS) {
        // =================== Phase 1a: Gram tile ===========================
        const int b = (bidx >= NUPPER) ? 1 : 0;
        const int t = bidx - b * NUPPER;

        const float* src = mu_in + b * IMG_ELEMS;
        for (int i = tid; i < IMG_ELEMS; i += 256) img[i] = src[i];
        __syncthreads();

        int ti = 0, rem = t;
        while (rem >= NT - ti) { rem -= NT - ti; ti++; }
        const int tj = ti + rem;

        const int tx = tid & 15;
        const int ty = tid >> 4;
        const int p0 = ti * TILE;
        const int q0 = tj * TILE;

        int basep[8], baseq[8];
        #pragma unroll
        for (int r = 0; r < 8; r++) {
            int p = p0 + ty * 8 + r;
            int pc = (p < PP) ? p : 0;
            int ph = pc / OH, pw = pc - ph * OH;
            basep[r] = ph * HH + pw;
        }
        #pragma unroll
        for (int s = 0; s < 8; s++) {
            int q = q0 + tx + s * 16;
            int qc = (q < PP) ? q : 0;
            int qh = qc / OH, qw = qc - qh * OH;
            baseq[s] = qh * HH + qw;
        }

        u64 acc[8][4];
        #pragma unroll
        for (int r = 0; r < 8; r++)
            #pragma unroll
            for (int h = 0; h < 4; h++) acc[r][h] = 0ULL;

        #pragma unroll 1
        for (int c = 0; c < CIN; c++) {
            int bp[8], bq[8];
            const int coff = c * (HH * HH);
            #pragma unroll
            for (int r = 0; r < 8; r++) bp[r] = basep[r] + coff;
            #pragma unroll
            for (int s = 0; s < 8; s++) bq[s] = baseq[s] + coff;

            #pragma unroll
            for (int i = 0; i < KSZ; i++) {
                #pragma unroll
                for (int j = 0; j < KSZ; j++) {
                    const int off = i * HH + j;
                    float av[8], bv[8];
                    #pragma unroll
                    for (int r = 0; r < 8; r++) av[r] = img[bp[r] + off];
                    #pragma unroll
                    for (int s = 0; s < 8; s++) bv[s] = img[bq[s] + off];

                    u64 avp[8], bvp[4];
                    #pragma unroll
                    for (int r = 0; r < 8; r++) avp[r] = pack2(av[r], av[r]);
                    #pragma unroll
                    for (int h = 0; h < 4; h++) bvp[h] = pack2(bv[2*h], bv[2*h+1]);

                    #pragma unroll
                    for (int r = 0; r < 8; r++)
                        #pragma unroll
                        for (int h = 0; h < 4; h++)
                            fma2(acc[r][h], avp[r], bvp[h]);
                }
            }
        }

        float* gbase = g_xxT + (size_t)b * PP * PP;

        #pragma unroll
        for (int r = 0; r < 8; r++) {
            int p = p0 + ty * 8 + r;
            if (p >= PP) continue;
            float* row = gbase + (size_t)p * PP;
            #pragma unroll
            for (int h = 0; h < 4; h++) {
                float2 f = unpack2(acc[r][h]);
                int q1 = q0 + tx + 32 * h;
                int q2 = q1 + 16;
                if (q1 < PP) row[q1] = f.x;
                if (q2 < PP) row[q2] = f.y;
            }
        }

        if (ti != tj) {
            const int pbase = p0 + ty * 8;
            #pragma unroll
            for (int s = 0; s < 8; s++) {
                int q = q0 + tx + 16 * s;
                if (q >= PP) continue;
                float4 v0, v1;
                {
                    float2 a0 = unpack2(acc[0][s >> 1]);
                    float2 a1 = unpack2(acc[1][s >> 1]);
                    float2 a2 = unpack2(acc[2][s >> 1]);
                    float2 a3 = unpack2(acc[3][s >> 1]);
                    float2 a4 = unpack2(acc[4][s >> 1]);
                    float2 a5 = unpack2(acc[5][s >> 1]);
                    float2 a6 = unpack2(acc[6][s >> 1]);
                    float2 a7 = unpack2(acc[7][s >> 1]);
                    if (s & 1) {
                        v0 = make_float4(a0.y, a1.y, a2.y, a3.y);
                        v1 = make_float4(a4.y, a5.y, a6.y, a7.y);
                    } else {
                        v0 = make_float4(a0.x, a1.x, a2.x, a3.x);
                        v1 = make_float4(a4.x, a5.x, a6.x, a7.x);
                    }
                }
                float* row = gbase + (size_t)q * PP + pbase;
                if (pbase < PP)     *(float4*)row       = v0;
                if (pbase + 4 < PP) *(float4*)(row + 4) = v1;
            }
        }
    } else {
        // =================== Phase 1b: mu conv =============================
        const int mi = bidx - GRAM_CTAS;     // 0..23
        #pragma unroll 1
        for (int m = mi; m < BATCH * KN; m += MU_CTAS) {
            const int b  = m >> 4;
            const int kn = m & 15;
            const float* im = mu_in + b * IMG_ELEMS;
            const float* w  = w_mu + kn * WSZ;
            float* outp = mu_out + ((size_t)b * KN + kn) * (OH * OH);

            #pragma unroll 1
            for (int pass = 0; pass < 2; pass++) {
                int base[4];
                bool valid[4];
                #pragma unroll
                for (int k = 0; k < 4; k++) {
                    int pos = tid + (pass * 4 + k) * 256;
                    valid[k] = (pos < OH * OH);
                    int pc = valid[k] ? pos : 0;
                    int oy = pc / OH, ox = pc - oy * OH;
                    base[k] = oy * HH + ox;
                }
                float acc[4] = {0.f, 0.f, 0.f, 0.f};
                #pragma unroll
                for (int c = 0; c < CIN; c++) {
                    const float* imc = im + c * HH * HH;
                    const float* wc  = w + c * KSZ * KSZ;
                    #pragma unroll
                    for (int i = 0; i < KSZ; i++)
                        #pragma unroll
                        for (int j = 0; j < KSZ; j++) {
                            const float wv = __ldg(&wc[i * KSZ + j]);
                            const int off = i * HH + j;
                            #pragma unroll
                            for (int k = 0; k < 4; k++)
                                acc[k] = fmaf(__ldg(&imc[base[k] + off]), wv, acc[k]);
                        }
                }
                #pragma unroll
                for (int k = 0; k < 4; k++)
                    if (valid[k]) outp[tid + (pass * 4 + k) * 256] = acc[k];
            }
        }
    }

    // =================== Grid barrier (epoch counter) =======================
    __threadfence();      // make this CTA's global stores visible device-wide
    __syncthreads();      // all threads of the CTA done before thread0 arrives
    if (tid == 0) {
        u64 ticket = atomicAdd(&g_bar, 1ULL);
        u64 target = (ticket / GRID_SZ + 1ULL) * GRID_SZ;
        u64 v;
        do {
            asm volatile("ld.acquire.gpu.u64 %0, [%1];" : "=l"(v) : "l"(&g_bar));
        } while (v < target);
    }
    __syncthreads();

    // =================== Phase 2: scale-broadcast ===========================
    const size_t planeStride = (size_t)PP * PP;
    const int vb0 = bidx * VB_PER;
    const int vb1 = (vb0 + VB_PER < TOT_VB) ? vb0 + VB_PER : TOT_VB;

    #pragma unroll 1
    for (int vb = vb0; vb < vb1; vb++) {
        const int khalf = (vb >= SCALE_BLOCKS) ? 1 : 0;
        const int blk   = vb - khalf * SCALE_BLOCKS;
        const int idx   = blk * 256 + tid;
        if (idx >= SCALE_TOTAL) continue;

        const int qv = idx % QV;
        const int p  = (idx / QV) % PP;
        const int b  = idx / (QV * PP);

        const float4 v = __ldcg((const float4*)&g_xxT[((size_t)b * PP + p) * PP + qv * 4]);

        float* o = sigma + ((size_t)b * KN + khalf * KNH) * planeStride
                         + (size_t)p * PP + qv * 4;
        #pragma unroll
        for (int k = 0; k < KNH; k++) {
            const float s = sp[khalf * KNH + k];
            float4 w;
            w.x = v.x * s; w.y = v.y * s; w.z = v.z * s; w.w = v.w * s;
            __stcs((float4*)o, w);
            o += planeStride;
        }
    }
}

extern "C" void kernel_launch(void* const* d_in, const int* in_sizes, int n_in,
                              void* d_out, int out_size)
{
    const float* mu_in   = (const float*)d_in[0];
    const float* w_mu    = (const float*)d_in[1];
    const float* w_sigma = (const float*)d_in[2];

    float* out    = (float*)d_out;
    float* mu_out = out;
    float* sigma  = out + (size_t)BATCH * KN * OH * OH;

    vdp_fused_kernel<<<GRID_SZ, 256>>>(mu_in, w_mu, w_sigma, mu_out, sigma);
}

// round 17
// speedup vs baseline: 1.1283x; 1.1280x over previous
#include <cuda_runtime.h>

#define KSZ   5
#define CIN   3
#define BATCH 2
#define HH    48
#define KN    16
#define OH    44
#define PP    1936            // OH*OH
#define IMG_ELEMS (CIN*HH*HH) // 6912
#define WSZ   (CIN*KSZ*KSZ)   // 75

#define TILE    128
#define NT      16            // tiles per dim
#define NUPPER  (NT * (NT + 1) / 2)   // 136 upper-triangular tiles
#define QV      (PP / 4)      // 484 float4 per row

#define KNH          8                                 // kn planes per scale block (measured optimum)
#define MU_BLOCKS    (BATCH * KN)                      // 32, scheduled FIRST
#define SCALE_TOTAL  (BATCH * PP * QV)                 // 1,874,048 vec4 units
#define SCALE_BLOCKS ((SCALE_TOTAL + 255) / 256)       // 7321 per kn-half

typedef unsigned long long u64;

// 30 MB scratch for the unscaled Gram matrix xxT[b, p, q]
__device__ float g_xxT[(size_t)BATCH * PP * PP];

__device__ __forceinline__ u64 pack2(float lo, float hi) {
    u64 r; asm("mov.b64 %0, {%1,%2};" : "=l"(r) : "f"(lo), "f"(hi)); return r;
}
__device__ __forceinline__ void fma2(u64 &d, u64 a, u64 b) {
    asm("fma.rn.f32x2 %0, %1, %2, %0;" : "+l"(d) : "l"(a), "l"(b));
}
__device__ __forceinline__ float2 unpack2(u64 v) {
    float2 f; asm("mov.b64 {%0,%1}, %2;" : "=f"(f.x), "=f"(f.y) : "l"(v)); return f;
}

// ---------------------------------------------------------------------------
// Kernel A (measured-good): pure Gram.
// Grid (136, 1, 2) = 272 CTAs: one wave at 2 CTAs/SM. launch_dependents is
// raised early so dependent CTAs are resident by the time this grid
// completes; griddepcontrol.wait in the consumer carries the memory
// guarantee.
// ---------------------------------------------------------------------------
__global__ __launch_bounds__(256, 2)
void vdp_gram_kernel(const float* __restrict__ mu_in)
{
    __shared__ float img[IMG_ELEMS];

    const int tid = threadIdx.x;
    const int b   = blockIdx.z;

    const float* src = mu_in + b * IMG_ELEMS;
    for (int i = tid; i < IMG_ELEMS; i += 256) img[i] = src[i];
    __syncthreads();

    asm volatile("griddepcontrol.launch_dependents;");

    int ti = 0, rem = blockIdx.x;
    while (rem >= NT - ti) { rem -= NT - ti; ti++; }
    const int tj = ti + rem;

    const int tx = tid & 15;
    const int ty = tid >> 4;
    const int p0 = ti * TILE;
    const int q0 = tj * TILE;

    int basep[8], baseq[8];
    #pragma unroll
    for (int r = 0; r < 8; r++) {
        int p = p0 + ty * 8 + r;
        int pc = (p < PP) ? p : 0;
        int ph = pc / OH, pw = pc - ph * OH;
        basep[r] = ph * HH + pw;
    }
    #pragma unroll
    for (int s = 0; s < 8; s++) {
        int q = q0 + tx + s * 16;
        int qc = (q < PP) ? q : 0;
        int qh = qc / OH, qw = qc - qh * OH;
        baseq[s] = qh * HH + qw;
    }

    u64 acc[8][4];
    #pragma unroll
    for (int r = 0; r < 8; r++)
        #pragma unroll
        for (int h = 0; h < 4; h++) acc[r][h] = 0ULL;

    #pragma unroll 1
    for (int c = 0; c < CIN; c++) {
        int bp[8], bq[8];
        const int coff = c * (HH * HH);
        #pragma unroll
        for (int r = 0; r < 8; r++) bp[r] = basep[r] + coff;
        #pragma unroll
        for (int s = 0; s < 8; s++) bq[s] = baseq[s] + coff;

        #pragma unroll
        for (int i = 0; i < KSZ; i++) {
            #pragma unroll
            for (int j = 0; j < KSZ; j++) {
                const int off = i * HH + j;
                float av[8], bv[8];
                #pragma unroll
                for (int r = 0; r < 8; r++) av[r] = img[bp[r] + off];
                #pragma unroll
                for (int s = 0; s < 8; s++) bv[s] = img[bq[s] + off];

                u64 avp[8], bvp[4];
                #pragma unroll
                for (int r = 0; r < 8; r++) avp[r] = pack2(av[r], av[r]);
                #pragma unroll
                for (int h = 0; h < 4; h++) bvp[h] = pack2(bv[2*h], bv[2*h+1]);

                #pragma unroll
                for (int r = 0; r < 8; r++)
                    #pragma unroll
                    for (int h = 0; h < 4; h++)
                        fma2(acc[r][h], avp[r], bvp[h]);
            }
        }
    }

    float* gbase = g_xxT + (size_t)b * PP * PP;

    #pragma unroll
    for (int r = 0; r < 8; r++) {
        int p = p0 + ty * 8 + r;
        if (p >= PP) continue;
        float* row = gbase + (size_t)p * PP;
        #pragma unroll
        for (int h = 0; h < 4; h++) {
            float2 f = unpack2(acc[r][h]);
            int q1 = q0 + tx + 32 * h;
            int q2 = q1 + 16;
            if (q1 < PP) row[q1] = f.x;
            if (q2 < PP) row[q2] = f.y;
        }
    }

    if (ti != tj) {
        const int pbase = p0 + ty * 8;
        #pragma unroll
        for (int s = 0; s < 8; s++) {
            int q = q0 + tx + 16 * s;
            if (q >= PP) continue;
            float4 v0, v1;
            {
                float2 a0 = unpack2(acc[0][s >> 1]);
                float2 a1 = unpack2(acc[1][s >> 1]);
                float2 a2 = unpack2(acc[2][s >> 1]);
                float2 a3 = unpack2(acc[3][s >> 1]);
                float2 a4 = unpack2(acc[4][s >> 1]);
                float2 a5 = unpack2(acc[5][s >> 1]);
                float2 a6 = unpack2(acc[6][s >> 1]);
                float2 a7 = unpack2(acc[7][s >> 1]);
                if (s & 1) {
                    v0 = make_float4(a0.y, a1.y, a2.y, a3.y);
                    v1 = make_float4(a4.y, a5.y, a6.y, a7.y);
                } else {
                    v0 = make_float4(a0.x, a1.x, a2.x, a3.x);
                    v1 = make_float4(a4.x, a5.x, a6.x, a7.x);
                }
            }
            float* row = gbase + (size_t)q * PP + pbase;
            if (pbase < PP)     *(float4*)row       = v0;
            if (pbase + 4 < PP) *(float4*)(row + 4) = v1;
        }
    }
}

// ---------------------------------------------------------------------------
// Kernel B: blocks [0, 32)  : mu conv (no xxT dependency -> NO wait).
//           blocks [32, ...): sigma = xxT * softplus(w_sigma[kn]).
// kn split into 2 halves across blocks: each block writes 8 planes (measured
// optimum: fewer write streams/thread than 16, better amortization than 4).
// One float4 per thread, consecutive lanes -> consecutive 16B (dense 512B
// per STG.128).
// ---------------------------------------------------------------------------
__global__ __launch_bounds__(256, 6)
void vdp_scale_kernel(const float* __restrict__ w_sigma,
                      const float* __restrict__ mu_in,
                      const float* __restrict__ w_mu,
                      float* __restrict__ mu_out,
                      float* __restrict__ sigma)
{
    const int tid = threadIdx.x;

    if (blockIdx.x < MU_BLOCKS) {
        // ---------------- mean conv plane: 2 passes of 4-way ILP ------------
        const int b  = blockIdx.x >> 4;
        const int kn = blockIdx.x & 15;
        const float* im = mu_in + b * IMG_ELEMS;
        const float* w  = w_mu + kn * WSZ;
        float* outp = mu_out + ((size_t)b * KN + kn) * (OH * OH);

        #pragma unroll 1
        for (int pass = 0; pass < 2; pass++) {
            int base[4];
            bool valid[4];
            #pragma unroll
            for (int k = 0; k < 4; k++) {
                int pos = tid + (pass * 4 + k) * 256;
                valid[k] = (pos < OH * OH);
                int pc = valid[k] ? pos : 0;
                int oy = pc / OH, ox = pc - oy * OH;
                base[k] = oy * HH + ox;
            }

            float acc[4] = {0.f, 0.f, 0.f, 0.f};

            #pragma unroll
            for (int c = 0; c < CIN; c++) {
                const float* imc = im + c * HH * HH;
                const float* wc  = w + c * KSZ * KSZ;
                #pragma unroll
                for (int i = 0; i < KSZ; i++) {
                    #pragma unroll
                    for (int j = 0; j < KSZ; j++) {
                        const float wv = __ldg(&wc[i * KSZ + j]);
                        const int off = i * HH + j;
                        #pragma unroll
                        for (int k = 0; k < 4; k++)
                            acc[k] = fmaf(__ldg(&imc[base[k] + off]), wv, acc[k]);
                    }
                }
            }

            #pragma unroll
            for (int k = 0; k < 4; k++)
                if (valid[k]) outp[tid + (pass * 4 + k) * 256] = acc[k];
        }
        return;
    }

    // Prologue (independent of xxT): softplus + index math
    __shared__ float sp[KN];
    if (tid < KN) sp[tid] = log1pf(expf(w_sigma[tid]));
    __syncthreads();

    const int lin   = (int)blockIdx.x - MU_BLOCKS;
    const int khalf = lin / SCALE_BLOCKS;          // 0 or 1
    const int blk   = lin - khalf * SCALE_BLOCKS;

    int idx = blk * 256 + tid;
    if (idx >= SCALE_TOTAL) return;

    int qv = idx % QV;
    int p  = (idx / QV) % PP;
    int b  = idx / (QV * PP);

    const size_t planeStride = (size_t)PP * PP;
    const float* gsrc = &g_xxT[((size_t)b * PP + p) * PP + qv * 4];
    float* o = sigma + ((size_t)b * KN + khalf * KNH) * planeStride
                     + (size_t)p * PP + qv * 4;

    // Gate the xxT read on the gram grid's completion (memory-visible).
    asm volatile("griddepcontrol.wait;" ::: "memory");

    const float4 v = __ldcg((const float4*)gsrc);

    #pragma unroll
    for (int k = 0; k < KNH; k++) {
        const float s = sp[khalf * KNH + k];
        float4 w;
        w.x = v.x * s; w.y = v.y * s; w.z = v.z * s; w.w = v.w * s;
        __stcs((float4*)o, w);
        o += planeStride;
    }
}

extern "C" void kernel_launch(void* const* d_in, const int* in_sizes, int n_in,
                              void* d_out, int out_size)
{
    const float* mu_in   = (const float*)d_in[0];
    const float* w_mu    = (const float*)d_in[1];
    const float* w_sigma = (const float*)d_in[2];

    float* out    = (float*)d_out;
    float* mu_out = out;
    float* sigma  = out + (size_t)BATCH * KN * OH * OH;

    // Primary: gram (plain launch)
    dim3 gridA(NUPPER, 1, BATCH);   // 272 CTAs: one wave at 2/SM
    vdp_gram_kernel<<<gridA, 256>>>(mu_in);

    // Secondary: scale(+mu) with programmatic dependency.
    cudaLaunchConfig_t cfg = {};
    cfg.gridDim  = dim3(MU_BLOCKS + 2 * SCALE_BLOCKS, 1, 1);
    cfg.blockDim = dim3(256, 1, 1);
    cfg.dynamicSmemBytes = 0;
    cfg.stream = 0;

    cudaLaunchAttribute attrs[1];
    attrs[0].id = cudaLaunchAttributeProgrammaticStreamSerialization;
    attrs[0].val.programmaticStreamSerializationAllowed = 1;
    cfg.attrs = attrs;
    cfg.numAttrs = 1;

    cudaError_t err = cudaLaunchKernelEx(&cfg, vdp_scale_kernel,
                                         w_sigma, mu_in, w_mu, mu_out, sigma);
    if (err != cudaSuccess) {
        vdp_scale_kernel<<<MU_BLOCKS + 2 * SCALE_BLOCKS, 256>>>(w_sigma, mu_in,
                                                                w_mu, mu_out, sigma);
    }
}